// round 13
// baseline (speedup 1.0000x reference)
#include <cuda_runtime.h>

#define NBINS 32
#define NROWS 34                  /* row 0 = identity-low, 1..32 real, 33 = identity-high */
#define NDIM 64
#define NCELL 66                  /* cells 0..65 via floor(65*sat(0.1v+0.5)) */
#define RMIN (-5.0f)
#define THREADS 768               /* 2 CTAs/SM -> 1536 thr = 48 warps, 40-reg cap */
#define BLOCKS 296                /* 148 SMs x 2 CTAs: one persistent wave */
#define STRIDE (BLOCKS * THREADS) /* 227328, compile-time, ==0 mod 64 */
#define U 6                       /* pipeline batch (proven at 40 regs) */

/* smem layout (all [row][dim]: consecutive lanes = consecutive dims = no
   bank conflicts regardless of divergent row index):
   rec  [NROWS][NDIM] float4 {xk, yk, (A,dk) bf16x2, (C,D) bf16x2}  34816 B
   cell [NCELL][NDIM] float  (bnd | jlo in low 6 bits)              16896 B
   hi   [NDIM] float (top knot, cell build only)                      256 B
   -> 51968 B, 2 CTAs/SM */
#define OFF_CELL 34816
#define OFF_HI   (34816 + 16896)
#define SMEM_BYTES (OFF_HI + 256)

/* round-to-nearest-even bf16, returned as the high-16 bit pattern */
__device__ __forceinline__ unsigned bf16_hi(float f)
{
    const unsigned u = __float_as_uint(f);
    return (u + 0x7FFFu + ((u >> 16) & 1u)) & 0xFFFF0000u;
}
/* pack two bf16: lo in bits[0:16), hi in bits[16:32) */
__device__ __forceinline__ float pack_bf(float lo, float hi)
{
    return __uint_as_float(bf16_hi(hi) | (bf16_hi(lo) >> 16));
}

__device__ __forceinline__ int bin_of(float v, const float* __restrict__ celld)
{
    /* FFMA.SAT folds both clamps: c = floor(65*sat(0.1v+0.5)) in [0,65] */
    const float ts = __saturatef(fmaf(v, 0.1f, 0.5f));
    const int c = __float2int_rd(ts * 65.0f);
    const int b = __float_as_int(celld[c * NDIM]);
    /* low 6 bits of boundary float hold jlo; ~63-ulp boundary shift is
       harmless: the spline is continuous across knots */
    return (b & 63) + ((v >= __int_as_float(b)) ? 1 : 0);
}

__device__ __forceinline__ float eval1(float v, int j,
                                       const float4* __restrict__ recd)
{
    const float4 r = recd[j * NDIM];
    const float u = v - r.x;
    /* bf16 unpack by bit ops: no conversion-pipe F2F on the critical path */
    const unsigned ab = __float_as_uint(r.z);
    const unsigned cd = __float_as_uint(r.w);
    const float A  = __uint_as_float(ab << 16);
    const float dk = __uint_as_float(ab & 0xFFFF0000u);
    const float C  = __uint_as_float(cd << 16);
    const float D  = __uint_as_float(cd & 0xFFFF0000u);
    const float num = u * fmaf(A, u, dk);
    const float den = fmaf(u, fmaf(C, u, D), 1.0f);
    float rc;
    asm("rcp.approx.f32 %0, %1;" : "=f"(rc) : "f"(den));
    return fmaf(num, rc, r.y);   /* identity rows: u=v, num=v, den=1 -> v */
}

__device__ __forceinline__ void eval_batch(
    const float* __restrict__ xv,
    const float* __restrict__ celld,
    const float4* __restrict__ recd,
    float* __restrict__ out, int i)
{
    int jj[U];
    #pragma unroll
    for (int u = 0; u < U; ++u) jj[u] = bin_of(xv[u], celld);
    #pragma unroll
    for (int u = 0; u < U; ++u)
        __stcs(out + i + u * STRIDE, eval1(xv[u], jj[u], recd));
}

__global__ __launch_bounds__(THREADS, 2) void rqspline_kernel(
    const float* __restrict__ x,
    const float* __restrict__ bw,
    const float* __restrict__ bh,
    const float* __restrict__ ks,
    float* __restrict__ out,
    int total)
{
    extern __shared__ __align__(16) char smem[];
    float4* rec  = (float4*)smem;
    float*  cell = (float*) (smem + OFF_CELL);
    float*  hi   = (float*) (smem + OFF_HI);

    const int t = threadIdx.x;
    const int tid = blockIdx.x * THREADS + t;

    /* ---- prefetch batch 0 BEFORE table build: LDGs fly during build ---- */
    float xc[U];
    const bool full0 = (tid + (U - 1) * STRIDE < total);
    if (full0) {
        #pragma unroll
        for (int u = 0; u < U; ++u) xc[u] = __ldcs(x + tid + u * STRIDE);
    }

    /* ---- phase 1: per-dim records; rows 0 and 33 encode identity ---- */
    if (t < NDIM) {
        float4 rid;
        rid.x = 0.0f; rid.y = 0.0f;
        rid.z = pack_bf(0.0f, 1.0f);   /* A=0, dk=1 (both bf16-exact) */
        rid.w = pack_bf(0.0f, 0.0f);   /* C=0, D=0 */
        rec[t] = rid;
        rec[(NROWS - 1) * NDIM + t] = rid;

        float cx = RMIN, cy = RMIN;
        #pragma unroll
        for (int jb = 0; jb < NBINS; ++jb) {
            const float nx = cx + bw[t * NBINS + jb];  /* reference fp32 cumsum */
            const float ny = cy + bh[t * NBINS + jb];
            const float wf = nx - cx;
            const float hf = ny - cy;
            const float dk  = (jb == 0) ? 1.0f : ks[t * (NBINS - 1) + jb - 1];
            const float dk1 = (jb == NBINS - 1) ? 1.0f : ks[t * (NBINS - 1) + jb];

            const float s = hf / wf;
            const float c = dk + dk1 - 2.0f * s;
            const float A = (s - dk) / wf;
            const float C = -c / (hf * wf);
            const float D = c / hf;

            float4 r;
            r.x = cx; r.y = cy;
            r.z = pack_bf(A, dk);
            r.w = pack_bf(C, D);
            rec[(jb + 1) * NDIM + t] = r;
            cx = nx; cy = ny;
        }
        hi[t] = cx;                /* kx[32] */
    }
    __syncthreads();

    /* ---- phase 2: cell table; boundaries read from rec[j+1].x ---- */
    const float* recf = (const float*)rec;
    for (int e = t; e < NCELL * NDIM; e += THREADS) {
        const int c = e >> 6, d = e & (NDIM - 1);
        float bnd; int jlo;
        if (c == 0) {              /* spans (-inf, first cell end) */
            bnd = RMIN; jlo = 0;   /* v<-5 -> row 0; v>=-5 -> row 1 */
        } else {
            const float cs = RMIN + (float)c * (10.0f / 65.0f);
            int j0 = min(c >> 1, NBINS - 1);
            while (j0 > 0 &&
                   recf[((j0 + 1) << 8) + (d << 2)] > cs) --j0;
            while (j0 < NBINS - 1 &&
                   recf[((j0 + 2) << 8) + (d << 2)] <= cs) ++j0;
            jlo = j0 + 1;
            bnd = (j0 + 1 < NBINS) ? recf[((j0 + 2) << 8) + (d << 2)] : hi[d];
        }
        cell[c * NDIM + d] =
            __int_as_float((__float_as_int(bnd) & ~63) | jlo);
    }
    __syncthreads();

    /* ---- phase 3: software-pipelined streaming eval ---- */
    const int d = tid & (NDIM - 1);      /* loop-invariant: STRIDE % 64 == 0 */
    const float4* recd  = rec  + d;
    const float*  celld = cell + d;

    int i = tid;
    for (; i + (2 * U - 1) * STRIDE < total; i += U * STRIDE) {
        float xn[U];
        #pragma unroll
        for (int u = 0; u < U; ++u)          /* next batch LDGs in flight */
            xn[u] = __ldcs(x + i + (U + u) * STRIDE);
        eval_batch(xc, celld, recd, out, i);
        #pragma unroll
        for (int u = 0; u < U; ++u) xc[u] = xn[u];
    }
    if (full0 && i + (U - 1) * STRIDE < total) {
        eval_batch(xc, celld, recd, out, i);
        i += U * STRIDE;
    }
    for (; i < total; i += STRIDE) {
        const float v = __ldcs(x + i);
        __stcs(out + i, eval1(v, bin_of(v, celld), recd));
    }
}

extern "C" void kernel_launch(void* const* d_in, const int* in_sizes, int n_in,
                              void* d_out, int out_size) {
    const float* x  = (const float*)d_in[0];
    const float* bw = (const float*)d_in[1];
    const float* bh = (const float*)d_in[2];
    const float* ks = (const float*)d_in[3];
    float* out = (float*)d_out;
    const int total = in_sizes[0];

    cudaFuncSetAttribute(rqspline_kernel,
                         cudaFuncAttributeMaxDynamicSharedMemorySize, SMEM_BYTES);
    rqspline_kernel<<<BLOCKS, THREADS, SMEM_BYTES>>>(x, bw, bh, ks, out, total);
}

// round 14
// speedup vs baseline: 1.0039x; 1.0039x over previous
#include <cuda_runtime.h>
#include <cuda_fp16.h>

#define NBINS 32
#define NROWS 34                  /* row 0 = identity-low, 1..32 real, 33 = identity-high */
#define NDIM 64
#define NCELL 66                  /* cells 0..65 via floor(65*sat(0.1v+0.5)) */
#define RMIN (-5.0f)
#define THREADS 768               /* 2 CTAs/SM -> 1536 thr = 48 warps, 40-reg cap */
#define BLOCKS 296                /* 148 SMs x 2 CTAs: one persistent wave */
#define STRIDE (BLOCKS * THREADS) /* 227328, compile-time, ==0 mod 64 */
#define U 6                       /* pipeline batch (proven at 40 regs) */

/* smem layout (all [row][dim]: consecutive lanes = consecutive dims = no
   bank conflicts regardless of divergent row index):
   rec  [NROWS][NDIM] float4 {xk, yk, (A,dk) f16x2, (C,D) f16x2}  34816 B
   cell [NCELL][NDIM] float  (bnd | jlo in low 6 bits)            16896 B
   hi   [NDIM] float (top knot, cell build only)                    256 B
   -> 51968 B, 2 CTAs/SM */
#define OFF_CELL 34816
#define OFF_HI   (34816 + 16896)
#define SMEM_BYTES (OFF_HI + 256)

__device__ __forceinline__ int bin_of(float v, const float* __restrict__ celld)
{
    /* FFMA.SAT folds both clamps: c = floor(65*sat(0.1v+0.5)) in [0,65] */
    const float ts = __saturatef(fmaf(v, 0.1f, 0.5f));
    const int c = __float2int_rd(ts * 65.0f);
    const int b = __float_as_int(celld[c * NDIM]);
    /* low 6 bits of boundary float hold jlo; ~63-ulp boundary shift is
       harmless: the spline is continuous across knots */
    return (b & 63) + ((v >= __int_as_float(b)) ? 1 : 0);
}

__device__ __forceinline__ float eval1(float v, int j,
                                       const float4* __restrict__ recd)
{
    const float4 r = recd[j * NDIM];
    const float u = v - r.x;
    const float2 ab = __half22float2(*(const __half2*)&r.z);  /* A, dk */
    const float2 cd = __half22float2(*(const __half2*)&r.w);  /* C, D  */
    const float num = u * fmaf(ab.x, u, ab.y);
    const float den = fmaf(u, fmaf(cd.x, u, cd.y), 1.0f);
    float rc;
    asm("rcp.approx.f32 %0, %1;" : "=f"(rc) : "f"(den));
    return fmaf(num, rc, r.y);   /* identity rows: num=v, den=1 -> v */
}

__device__ __forceinline__ void eval_batch(
    const float* __restrict__ xv,
    const float* __restrict__ celld,
    const float4* __restrict__ recd,
    float* __restrict__ out, int i)
{
    int jj[U];
    #pragma unroll
    for (int u = 0; u < U; ++u) jj[u] = bin_of(xv[u], celld);
    #pragma unroll
    for (int u = 0; u < U; ++u)
        __stcs(out + i + u * STRIDE, eval1(xv[u], jj[u], recd));
}

__global__ __launch_bounds__(THREADS, 2) void rqspline_kernel(
    const float* __restrict__ x,
    const float* __restrict__ bw,
    const float* __restrict__ bh,
    const float* __restrict__ ks,
    float* __restrict__ out,
    int total)
{
    extern __shared__ __align__(16) char smem[];
    float4* rec  = (float4*)smem;
    float*  cell = (float*) (smem + OFF_CELL);
    float*  hi   = (float*) (smem + OFF_HI);

    const int t = threadIdx.x;
    const int tid = blockIdx.x * THREADS + t;

    /* ---- prefetch batch 0 BEFORE table build: LDGs fly during build ---- */
    float xc[U];
    const bool full0 = (tid + (U - 1) * STRIDE < total);
    if (full0) {
        #pragma unroll
        for (int u = 0; u < U; ++u) xc[u] = __ldcs(x + tid + u * STRIDE);
    }

    /* ---- phase 1: per-dim records; rows 0 and 33 encode identity ---- */
    if (t < NDIM) {
        const __half2 h01_id = __floats2half2_rn(0.0f, 1.0f);  /* A=0, dk=1 */
        const __half2 h23_id = __floats2half2_rn(0.0f, 0.0f);  /* C=0, D=0  */
        float4 rid;
        rid.x = 0.0f; rid.y = 0.0f;
        rid.z = __uint_as_float(*(const unsigned*)&h01_id);
        rid.w = __uint_as_float(*(const unsigned*)&h23_id);
        rec[t] = rid;
        rec[(NROWS - 1) * NDIM + t] = rid;

        float cx = RMIN, cy = RMIN;
        #pragma unroll
        for (int jb = 0; jb < NBINS; ++jb) {
            const float nx = cx + bw[t * NBINS + jb];  /* reference fp32 cumsum */
            const float ny = cy + bh[t * NBINS + jb];
            const float wf = nx - cx;
            const float hf = ny - cy;
            const float dk  = (jb == 0) ? 1.0f : ks[t * (NBINS - 1) + jb - 1];
            const float dk1 = (jb == NBINS - 1) ? 1.0f : ks[t * (NBINS - 1) + jb];

            const float s = hf / wf;
            const float c = dk + dk1 - 2.0f * s;
            const float A = (s - dk) / wf;
            const float C = -c / (hf * wf);
            const float D = c / hf;

            float4 r;
            r.x = cx; r.y = cy;
            const __half2 h01 = __floats2half2_rn(A, dk);
            const __half2 h23 = __floats2half2_rn(C, D);
            r.z = __uint_as_float(*(const unsigned*)&h01);
            r.w = __uint_as_float(*(const unsigned*)&h23);
            rec[(jb + 1) * NDIM + t] = r;
            cx = nx; cy = ny;
        }
        hi[t] = cx;                /* kx[32] */
    }
    __syncthreads();

    /* ---- phase 2: cell table; boundaries read from rec[j+1].x ---- */
    const float* recf = (const float*)rec;
    for (int e = t; e < NCELL * NDIM; e += THREADS) {
        const int c = e >> 6, d = e & (NDIM - 1);
        float bnd; int jlo;
        if (c == 0) {              /* spans (-inf, first cell end) */
            bnd = RMIN; jlo = 0;   /* v<-5 -> row 0; v>=-5 -> row 1 */
        } else {
            const float cs = RMIN + (float)c * (10.0f / 65.0f);
            int j0 = min(c >> 1, NBINS - 1);
            while (j0 > 0 &&
                   recf[((j0 + 1) << 8) + (d << 2)] > cs) --j0;
            while (j0 < NBINS - 1 &&
                   recf[((j0 + 2) << 8) + (d << 2)] <= cs) ++j0;
            jlo = j0 + 1;
            bnd = (j0 + 1 < NBINS) ? recf[((j0 + 2) << 8) + (d << 2)] : hi[d];
        }
        cell[c * NDIM + d] =
            __int_as_float((__float_as_int(bnd) & ~63) | jlo);
    }
    __syncthreads();

    /* ---- phase 3: software-pipelined streaming eval ---- */
    const int d = tid & (NDIM - 1);      /* loop-invariant: STRIDE % 64 == 0 */
    const float4* recd  = rec  + d;
    const float*  celld = cell + d;

    int i = tid;
    for (; i + (2 * U - 1) * STRIDE < total; i += U * STRIDE) {
        float xn[U];
        #pragma unroll
        for (int u = 0; u < U; ++u)          /* next batch LDGs in flight */
            xn[u] = __ldcs(x + i + (U + u) * STRIDE);
        eval_batch(xc, celld, recd, out, i);
        #pragma unroll
        for (int u = 0; u < U; ++u) xc[u] = xn[u];
    }
    if (full0 && i + (U - 1) * STRIDE < total) {
        eval_batch(xc, celld, recd, out, i);
        i += U * STRIDE;
    }
    for (; i < total; i += STRIDE) {
        const float v = __ldcs(x + i);
        __stcs(out + i, eval1(v, bin_of(v, celld), recd));
    }
}

extern "C" void kernel_launch(void* const* d_in, const int* in_sizes, int n_in,
                              void* d_out, int out_size) {
    const float* x  = (const float*)d_in[0];
    const float* bw = (const float*)d_in[1];
    const float* bh = (const float*)d_in[2];
    const float* ks = (const float*)d_in[3];
    float* out = (float*)d_out;
    const int total = in_sizes[0];

    cudaFuncSetAttribute(rqspline_kernel,
                         cudaFuncAttributeMaxDynamicSharedMemorySize, SMEM_BYTES);
    rqspline_kernel<<<BLOCKS, THREADS, SMEM_BYTES>>>(x, bw, bh, ks, out, total);
}

// round 16
// speedup vs baseline: 1.0205x; 1.0165x over previous
#include <cuda_runtime.h>
#include <cuda_fp16.h>

#define NBINS 32
#define NROWS 34                  /* row 0 = identity-low, 1..32 real, 33 = identity-high */
#define NDIM 64
#define NCELL 66                  /* cells 0..65 via floor(65*sat(0.1v+0.5)) */
#define RMIN (-5.0f)
#define THREADS 768               /* 2 CTAs/SM -> 1536 thr = 48 warps, 40-reg cap */
#define BLOCKS 296                /* 148 SMs x 2 CTAs: one persistent wave */
#define STRIDE (BLOCKS * THREADS) /* 227328, compile-time, ==0 mod 64 */
#define U 6                       /* pipeline batch (proven at 40 regs) */

/* smem layout (all [row][dim]: consecutive lanes = consecutive dims = no
   bank conflicts regardless of divergent row index):
   rec  [NROWS][NDIM] float4 {xk, yk, (A,dk) f16x2, (C,D) f16x2}  34816 B
   cell [NCELL][NDIM] float2 {boundary, row byte-offset bits}     33792 B
   hi   [NDIM] float (top knot, cell build only)                    256 B
   -> 68864 B, 2 CTAs/SM */
#define OFF_CELL 34816
#define OFF_HI   (34816 + 33792)
#define SMEM_BYTES (OFF_HI + 256)

/* returns byte offset of the spline row for v: cell lookup + one compare */
__device__ __forceinline__ int off_of(float v, const float2* __restrict__ celld)
{
    /* FFMA.SAT folds both clamps: c = floor(65*sat(0.1v+0.5)) in [0,65] */
    const float ts = __saturatef(fmaf(v, 0.1f, 0.5f));
    const int c = __float2int_rd(ts * 65.0f);
    const float2 ce = celld[c * NDIM];
    /* ce.y holds jlo*1024 (row byte stride = NDIM*16); exact boundary in ce.x */
    return __float_as_int(ce.y) + ((v >= ce.x) ? 1024 : 0);
}

__device__ __forceinline__ float eval1(float v, int off,
                                       const char* __restrict__ recd)
{
    const float4 r = *(const float4*)(recd + off);
    const float u = v - r.x;
    const float2 ab = __half22float2(*(const __half2*)&r.z);  /* A, dk */
    const float2 cd = __half22float2(*(const __half2*)&r.w);  /* C, D  */
    const float num = u * fmaf(ab.x, u, ab.y);
    const float den = fmaf(u, fmaf(cd.x, u, cd.y), 1.0f);
    return r.y + __fdividef(num, den);  /* identity rows: y = 0 + v/1 = v */
}

__device__ __forceinline__ void eval_batch(
    const float* __restrict__ xv,
    const float2* __restrict__ celld,
    const char* __restrict__ recd,
    float* __restrict__ out, int i)
{
    int oo[U];
    #pragma unroll
    for (int u = 0; u < U; ++u) oo[u] = off_of(xv[u], celld);
    #pragma unroll
    for (int u = 0; u < U; ++u)
        __stcs(out + i + u * STRIDE, eval1(xv[u], oo[u], recd));
}

__global__ __launch_bounds__(THREADS, 2) void rqspline_kernel(
    const float* __restrict__ x,
    const float* __restrict__ bw,
    const float* __restrict__ bh,
    const float* __restrict__ ks,
    float* __restrict__ out,
    int total)
{
    extern __shared__ __align__(16) char smem[];
    float4* rec  = (float4*)smem;
    float2* cell = (float2*)(smem + OFF_CELL);
    float*  hi   = (float*) (smem + OFF_HI);

    const int t = threadIdx.x;
    const int tid = blockIdx.x * THREADS + t;

    /* ---- prefetch batch 0 BEFORE table build: LDGs fly during build ---- */
    float xc[U];
    const bool full0 = (tid + (U - 1) * STRIDE < total);
    if (full0) {
        #pragma unroll
        for (int u = 0; u < U; ++u) xc[u] = __ldcs(x + tid + u * STRIDE);
    }

    /* ---- phase 1: per-dim records; rows 0 and 33 encode identity ---- */
    if (t < NDIM) {
        const __half2 h01_id = __floats2half2_rn(0.0f, 1.0f);  /* A=0, dk=1 */
        const __half2 h23_id = __floats2half2_rn(0.0f, 0.0f);  /* C=0, D=0  */
        float4 rid;
        rid.x = 0.0f; rid.y = 0.0f;
        rid.z = __uint_as_float(*(const unsigned*)&h01_id);
        rid.w = __uint_as_float(*(const unsigned*)&h23_id);
        rec[t] = rid;
        rec[(NROWS - 1) * NDIM + t] = rid;

        float cx = RMIN, cy = RMIN;
        #pragma unroll
        for (int jb = 0; jb < NBINS; ++jb) {
            const float nx = cx + bw[t * NBINS + jb];  /* reference fp32 cumsum */
            const float ny = cy + bh[t * NBINS + jb];
            const float wf = nx - cx;
            const float hf = ny - cy;
            const float dk  = (jb == 0) ? 1.0f : ks[t * (NBINS - 1) + jb - 1];
            const float dk1 = (jb == NBINS - 1) ? 1.0f : ks[t * (NBINS - 1) + jb];

            const float s = hf / wf;
            const float c = dk + dk1 - 2.0f * s;
            const float A = (s - dk) / wf;
            const float C = -c / (hf * wf);
            const float D = c / hf;

            float4 r;
            r.x = cx; r.y = cy;
            const __half2 h01 = __floats2half2_rn(A, dk);
            const __half2 h23 = __floats2half2_rn(C, D);
            r.z = __uint_as_float(*(const unsigned*)&h01);
            r.w = __uint_as_float(*(const unsigned*)&h23);
            rec[(jb + 1) * NDIM + t] = r;
            cx = nx; cy = ny;
        }
        hi[t] = cx;                /* kx[32] */
    }
    __syncthreads();

    /* ---- phase 2: cell table; boundaries read from rec[j+1].x ---- */
    const float* recf = (const float*)rec;
    for (int e = t; e < NCELL * NDIM; e += THREADS) {
        const int c = e >> 6, d = e & (NDIM - 1);
        float bnd; int jlo;
        if (c == 0) {              /* spans (-inf, first cell end) */
            bnd = RMIN; jlo = 0;   /* v<-5 -> row 0; v>=-5 -> row 1 */
        } else {
            const float cs = RMIN + (float)c * (10.0f / 65.0f);
            int j0 = min(c >> 1, NBINS - 1);
            while (j0 > 0 &&
                   recf[((j0 + 1) << 8) + (d << 2)] > cs) --j0;
            while (j0 < NBINS - 1 &&
                   recf[((j0 + 2) << 8) + (d << 2)] <= cs) ++j0;
            jlo = j0 + 1;
            bnd = (j0 + 1 < NBINS) ? recf[((j0 + 2) << 8) + (d << 2)] : hi[d];
        }
        cell[c * NDIM + d] =
            make_float2(bnd, __int_as_float(jlo << 10));  /* jlo * 1024 B */
    }
    __syncthreads();

    /* ---- phase 3: software-pipelined streaming eval ---- */
    const int d = tid & (NDIM - 1);      /* loop-invariant: STRIDE % 64 == 0 */
    const char*   recd  = (const char*)(rec + d);
    const float2* celld = cell + d;

    int i = tid;
    for (; i + (2 * U - 1) * STRIDE < total; i += U * STRIDE) {
        float xn[U];
        #pragma unroll
        for (int u = 0; u < U; ++u)          /* next batch LDGs in flight */
            xn[u] = __ldcs(x + i + (U + u) * STRIDE);
        eval_batch(xc, celld, recd, out, i);
        #pragma unroll
        for (int u = 0; u < U; ++u) xc[u] = xn[u];
    }
    if (full0 && i + (U - 1) * STRIDE < total) {
        eval_batch(xc, celld, recd, out, i);
        i += U * STRIDE;
    }
    for (; i < total; i += STRIDE) {
        const float v = __ldcs(x + i);
        __stcs(out + i, eval1(v, off_of(v, celld), recd));
    }
}

extern "C" void kernel_launch(void* const* d_in, const int* in_sizes, int n_in,
                              void* d_out, int out_size) {
    const float* x  = (const float*)d_in[0];
    const float* bw = (const float*)d_in[1];
    const float* bh = (const float*)d_in[2];
    const float* ks = (const float*)d_in[3];
    float* out = (float*)d_out;
    const int total = in_sizes[0];

    cudaFuncSetAttribute(rqspline_kernel,
                         cudaFuncAttributeMaxDynamicSharedMemorySize, SMEM_BYTES);
    rqspline_kernel<<<BLOCKS, THREADS, SMEM_BYTES>>>(x, bw, bh, ks, out, total);
}